// round 4
// baseline (speedup 1.0000x reference)
#include <cuda_runtime.h>
#include <math.h>

// ---------------- problem constants ----------------
#define Bb    2
#define Ss    2048
#define MTOK  4096          // Bb*Ss
#define DIMM  1024
#define Hh    8
#define QCc   128
#define QNOPE 96
#define QROPE 32
#define KVCc  128
#define KNOPE 64
#define KROPE 64
#define VHD   256
#define QKD   128           // q/k head dim
#define NBATCH 16           // Bb*Hh

// ---------------- scratch (device globals; no allocation) ----------------
__device__ float g_cq[MTOK * QCc];
__device__ float g_q[MTOK * 1024];
__device__ float g_ckvkr[MTOK * 192];
__device__ float g_ckv[MTOK * KVCc];
__device__ float g_kr[MTOK * KROPE];
__device__ float g_kv[MTOK * 2560];
__device__ float g_qs[NBATCH * Ss * QKD];
__device__ float g_ks[NBATCH * Ss * QKD];
__device__ float g_vs[NBATCH * Ss * VHD];
__device__ float g_sc[(long long)NBATCH * Ss * Ss];   // 268 MB
__device__ float g_attn2[NBATCH * Ss * VHD];
__device__ float g_attn[MTOK * 2048];

// ---------------- generic tiled SGEMM ----------------
// C[m,n] = alpha * sum_k A[m,k] * (TRANSB ? B[n,k] : B[k,n]) + bias[n]
// 128x128 block, BK=8, 256 threads, 8x8 micro-tile. Batched via blockIdx.z.
// Requirements: M % 128 == 0, K % 8 == 0, N % 4 == 0, lda/ldb % 4 == 0.
template <bool TRANSB>
__global__ void __launch_bounds__(256, 2)
sgemm_kernel(const float* __restrict__ A, int lda, long long sA,
             const float* __restrict__ Bp, int ldb, long long sB,
             const float* __restrict__ bias,
             float* __restrict__ C, int ldc, long long sC,
             int M, int N, int K, float alpha)
{
    __shared__ float As[8 * 132];
    __shared__ float Bs[8 * 132];

    const int z = blockIdx.z;
    A  += z * sA;
    Bp += z * sB;
    C  += z * sC;

    const int m0 = blockIdx.y * 128;
    const int n0 = blockIdx.x * 128;
    const int tid = threadIdx.x;
    const int tx = tid & 15;
    const int ty = tid >> 4;

    const int arow = tid >> 1;          // 0..127
    const int acol = (tid & 1) << 2;    // 0 or 4
    const int brow = tid >> 5;          // 0..7
    const int bcol = (tid & 31) << 2;   // 0..124

    float acc[8][8];
#pragma unroll
    for (int i = 0; i < 8; i++)
#pragma unroll
        for (int j = 0; j < 8; j++) acc[i][j] = 0.f;

    for (int kt = 0; kt < K; kt += 8) {
        // A tile -> transposed smem (As[k][m]); M,K always in-bounds here.
        float4 av = *reinterpret_cast<const float4*>(
            A + (long long)(m0 + arow) * lda + kt + acol);
        As[(acol + 0) * 132 + arow] = av.x;
        As[(acol + 1) * 132 + arow] = av.y;
        As[(acol + 2) * 132 + arow] = av.z;
        As[(acol + 3) * 132 + arow] = av.w;

        if (TRANSB) {
            // B is [N,K] row-major; load 128 n-rows x 8 k-cols, transpose into Bs[k][n]
            int gn = n0 + arow;
            float4 bv = make_float4(0.f, 0.f, 0.f, 0.f);
            if (gn < N)
                bv = *reinterpret_cast<const float4*>(
                    Bp + (long long)gn * ldb + kt + acol);
            Bs[(acol + 0) * 132 + arow] = bv.x;
            Bs[(acol + 1) * 132 + arow] = bv.y;
            Bs[(acol + 2) * 132 + arow] = bv.z;
            Bs[(acol + 3) * 132 + arow] = bv.w;
        } else {
            int gn = n0 + bcol;
            float4 bv = make_float4(0.f, 0.f, 0.f, 0.f);
            if (gn < N)   // N%4==0 -> whole float4 in or out
                bv = *reinterpret_cast<const float4*>(
                    Bp + (long long)(kt + brow) * ldb + gn);
            *reinterpret_cast<float4*>(&Bs[brow * 132 + bcol]) = bv;
        }
        __syncthreads();

#pragma unroll
        for (int k = 0; k < 8; k++) {
            float a[8], b[8];
            *reinterpret_cast<float4*>(&a[0]) =
                *reinterpret_cast<const float4*>(&As[k * 132 + ty * 8]);
            *reinterpret_cast<float4*>(&a[4]) =
                *reinterpret_cast<const float4*>(&As[k * 132 + ty * 8 + 4]);
            *reinterpret_cast<float4*>(&b[0]) =
                *reinterpret_cast<const float4*>(&Bs[k * 132 + tx * 8]);
            *reinterpret_cast<float4*>(&b[4]) =
                *reinterpret_cast<const float4*>(&Bs[k * 132 + tx * 8 + 4]);
#pragma unroll
            for (int i = 0; i < 8; i++)
#pragma unroll
                for (int j = 0; j < 8; j++)
                    acc[i][j] += a[i] * b[j];
        }
        __syncthreads();
    }

#pragma unroll
    for (int i = 0; i < 8; i++) {
        int gm = m0 + ty * 8 + i;
#pragma unroll
        for (int j = 0; j < 8; j++) {
            int gn = n0 + tx * 8 + j;
            if (gn < N) {
                float v = acc[i][j] * alpha;
                if (bias) v += bias[gn];
                C[(long long)gm * ldc + gn] = v;
            }
        }
    }
}

// ---------------- rmsnorm over 128 cols (in place) ----------------
__global__ void rmsnorm128_kernel(float* __restrict__ buf, const float* __restrict__ w)
{
    int row = blockIdx.x, tid = threadIdx.x;
    float v = buf[row * 128 + tid];
    float ss = v * v;
#pragma unroll
    for (int o = 16; o; o >>= 1) ss += __shfl_xor_sync(0xffffffffu, ss, o);
    __shared__ float red[4];
    if ((tid & 31) == 0) red[tid >> 5] = ss;
    __syncthreads();
    float tot = red[0] + red[1] + red[2] + red[3];
    float rs = rsqrtf(tot * (1.f / 128.f) + 1e-8f);
    buf[row * 128 + tid] = w[tid] * v * rs;
}

// ---------------- ckv rmsnorm + k_rope rope ----------------
__global__ void post_ckvkr_kernel(const float* __restrict__ in,
                                  const float* __restrict__ w,
                                  const int* __restrict__ pos,
                                  float* __restrict__ ckv,
                                  float* __restrict__ kr)
{
    int row = blockIdx.x, tid = threadIdx.x;   // 128 threads
    float v = in[row * 192 + tid];
    float ss = v * v;
#pragma unroll
    for (int o = 16; o; o >>= 1) ss += __shfl_xor_sync(0xffffffffu, ss, o);
    __shared__ float red[4];
    if ((tid & 31) == 0) red[tid >> 5] = ss;
    __syncthreads();
    float tot = red[0] + red[1] + red[2] + red[3];
    float rs = rsqrtf(tot * (1.f / 128.f) + 1e-8f);
    ckv[row * 128 + tid] = w[tid] * v * rs;

    if (tid < 32) {   // 32 rope pairs, head_dim 64
        float xe = in[row * 192 + 128 + 2 * tid];
        float xo = in[row * 192 + 128 + 2 * tid + 1];
        float invf = powf(10000.f, -(float)(2 * tid) / 64.f);
        float ang = (float)pos[row] * invf;
        float s, c;
        sincosf(ang, &s, &c);
        kr[row * 64 + 2 * tid]     = xe * c - xo * s;
        kr[row * 64 + 2 * tid + 1] = xe * s + xo * c;
    }
}

// ---------------- build q_states [16][2048][128] with rope ----------------
__global__ void build_q_kernel(const float* __restrict__ q,
                               const int* __restrict__ pos,
                               float* __restrict__ qs)
{
    int idx = blockIdx.x * blockDim.x + threadIdx.x;   // NBATCH*Ss*128
    int d = idx & 127;
    int t = idx >> 7;
    int qp = t & (Ss - 1);
    int zz = t >> 11;
    int b = zz >> 3, h = zz & 7;
    int row = b * Ss + qp;
    float val;
    if (d < 96) {
        val = q[row * 1024 + h * 96 + d];
    } else {
        int r = d - 96;
        int i = r >> 1;
        float xe = q[row * 1024 + 768 + h * 32 + 2 * i];
        float xo = q[row * 1024 + 768 + h * 32 + 2 * i + 1];
        float invf = powf(10000.f, -(float)(2 * i) / 32.f);
        float ang = (float)pos[row] * invf;
        float s, c;
        sincosf(ang, &s, &c);
        val = (r & 1) ? (xe * s + xo * c) : (xe * c - xo * s);
    }
    qs[idx] = val;
}

// ---------------- build k_states [16][2048][128] ----------------
__global__ void build_k_kernel(const float* __restrict__ kv,
                               const float* __restrict__ kr,
                               float* __restrict__ ks)
{
    int idx = blockIdx.x * blockDim.x + threadIdx.x;
    int d = idx & 127;
    int t = idx >> 7;
    int qp = t & (Ss - 1);
    int zz = t >> 11;
    int b = zz >> 3, h = zz & 7;
    int row = b * Ss + qp;
    ks[idx] = (d < 64) ? kv[row * 2560 + h * 64 + d] : kr[row * 64 + (d - 64)];
}

// ---------------- build v_states [16][2048][256] ----------------
__global__ void build_v_kernel(const float* __restrict__ kv, float* __restrict__ vs)
{
    int idx = blockIdx.x * blockDim.x + threadIdx.x;
    int d = idx & 255;
    int t = idx >> 8;
    int qp = t & (Ss - 1);
    int zz = t >> 11;
    int b = zz >> 3, h = zz & 7;
    int row = b * Ss + qp;
    vs[idx] = kv[row * 2560 + 512 + h * 256 + d];
}

// ---------------- row softmax over 2048 cols (register resident) ----------
__global__ void softmax_kernel(float* __restrict__ sc)
{
    float* p = sc + (long long)blockIdx.x * 2048;
    int tid = threadIdx.x;            // 256 threads, 8 cols each
    float v[8];
#pragma unroll
    for (int i = 0; i < 8; i++) v[i] = p[tid + 256 * i];
    float m = v[0];
#pragma unroll
    for (int i = 1; i < 8; i++) m = fmaxf(m, v[i]);
#pragma unroll
    for (int o = 16; o; o >>= 1) m = fmaxf(m, __shfl_xor_sync(0xffffffffu, m, o));
    __shared__ float redm[8];
    int lane = tid & 31, w = tid >> 5;
    if (lane == 0) redm[w] = m;
    __syncthreads();
    m = redm[0];
#pragma unroll
    for (int i = 1; i < 8; i++) m = fmaxf(m, redm[i]);

    float sum = 0.f;
#pragma unroll
    for (int i = 0; i < 8; i++) { v[i] = expf(v[i] - m); sum += v[i]; }
#pragma unroll
    for (int o = 16; o; o >>= 1) sum += __shfl_xor_sync(0xffffffffu, sum, o);
    __shared__ float reds[8];
    if (lane == 0) reds[w] = sum;
    __syncthreads();
    sum = 0.f;
#pragma unroll
    for (int i = 0; i < 8; i++) sum += reds[i];
    float inv = 1.f / sum;
#pragma unroll
    for (int i = 0; i < 8; i++) p[tid + 256 * i] = v[i] * inv;
}

// ---------------- permute attn2 [16][S][256] -> attn [B*S][H*256] ---------
__global__ void permute_kernel(const float* __restrict__ a2, float* __restrict__ a)
{
    int idx = blockIdx.x * blockDim.x + threadIdx.x;   // MTOK*2048
    int col = idx & 2047;
    int row = idx >> 11;
    int h = col >> 8;
    int d = col & 255;
    int b = row >> 11;
    int qp = row & (Ss - 1);
    a[idx] = a2[(((b << 3) + h) * Ss + qp) * 256 + d];
}

// ---------------- launch ----------------
extern "C" void kernel_launch(void* const* d_in, const int* in_sizes, int n_in,
                              void* d_out, int out_size)
{
    const float* x         = (const float*)d_in[0];
    const int*   pos       = (const int*)  d_in[1];
    const float* w_dq_w    = (const float*)d_in[2];
    const float* w_dq_b    = (const float*)d_in[3];
    const float* q_norm_w  = (const float*)d_in[4];
    const float* w_uq_qr_w = (const float*)d_in[5];
    const float* w_uq_qr_b = (const float*)d_in[6];
    const float* w_dkv_w   = (const float*)d_in[7];
    const float* w_dkv_b   = (const float*)d_in[8];
    const float* kv_norm_w = (const float*)d_in[9];
    const float* w_ukuv_w  = (const float*)d_in[10];
    const float* w_ukuv_b  = (const float*)d_in[11];
    const float* w_o_w     = (const float*)d_in[12];
    const float* w_o_b     = (const float*)d_in[13];
    float* out = (float*)d_out;

    float *p_cq, *p_q, *p_ckvkr, *p_ckv, *p_kr, *p_kv;
    float *p_qs, *p_ks, *p_vs, *p_sc, *p_attn2, *p_attn;
    cudaGetSymbolAddress((void**)&p_cq,    g_cq);
    cudaGetSymbolAddress((void**)&p_q,     g_q);
    cudaGetSymbolAddress((void**)&p_ckvkr, g_ckvkr);
    cudaGetSymbolAddress((void**)&p_ckv,   g_ckv);
    cudaGetSymbolAddress((void**)&p_kr,    g_kr);
    cudaGetSymbolAddress((void**)&p_kv,    g_kv);
    cudaGetSymbolAddress((void**)&p_qs,    g_qs);
    cudaGetSymbolAddress((void**)&p_ks,    g_ks);
    cudaGetSymbolAddress((void**)&p_vs,    g_vs);
    cudaGetSymbolAddress((void**)&p_sc,    g_sc);
    cudaGetSymbolAddress((void**)&p_attn2, g_attn2);
    cudaGetSymbolAddress((void**)&p_attn,  g_attn);

    const dim3 blk(256);
    const float scale = 0.08838834764831845f;   // 1/sqrt(128)

    // 1) cq_raw = x @ w_dq + b           [4096,128], K=1024
    sgemm_kernel<false><<<dim3(1, 32, 1), blk>>>(
        x, 1024, 0, w_dq_w, 128, 0, w_dq_b, p_cq, 128, 0, MTOK, 128, 1024, 1.f);
    // 2) rmsnorm(cq) in place
    rmsnorm128_kernel<<<MTOK, 128>>>(p_cq, q_norm_w);
    // 3) q = cq @ w_uq_qr + b            [4096,1024], K=128
    sgemm_kernel<false><<<dim3(8, 32, 1), blk>>>(
        p_cq, 128, 0, w_uq_qr_w, 1024, 0, w_uq_qr_b, p_q, 1024, 0, MTOK, 1024, 128, 1.f);
    // 4) ckv_kr = x @ w_dkv_kr + b       [4096,192], K=1024
    sgemm_kernel<false><<<dim3(2, 32, 1), blk>>>(
        x, 1024, 0, w_dkv_w, 192, 0, w_dkv_b, p_ckvkr, 192, 0, MTOK, 192, 1024, 1.f);
    // 5) rmsnorm(ckv) + rope(k_rope)
    post_ckvkr_kernel<<<MTOK, 128>>>(p_ckvkr, kv_norm_w, pos, p_ckv, p_kr);
    // 6) kv = ckv @ w_uk_uv + b          [4096,2560], K=128
    sgemm_kernel<false><<<dim3(20, 32, 1), blk>>>(
        p_ckv, 128, 0, w_ukuv_w, 2560, 0, w_ukuv_b, p_kv, 2560, 0, MTOK, 2560, 128, 1.f);
    // 7) build q_states / k_states / v_states per (b,h)
    build_q_kernel<<<(NBATCH * Ss * QKD) / 256, 256>>>(p_q, pos, p_qs);
    build_k_kernel<<<(NBATCH * Ss * QKD) / 256, 256>>>(p_kv, p_kr, p_ks);
    build_v_kernel<<<(NBATCH * Ss * VHD) / 256, 256>>>(p_kv, p_vs);
    // 8) scores = scale * Q @ K^T        batched 16x [2048,2048], K=128
    sgemm_kernel<true><<<dim3(16, 16, NBATCH), blk>>>(
        p_qs, QKD, (long long)Ss * QKD,
        p_ks, QKD, (long long)Ss * QKD,
        nullptr,
        p_sc, Ss, (long long)Ss * Ss,
        Ss, Ss, QKD, scale);
    // 9) softmax rows
    softmax_kernel<<<NBATCH * Ss, 256>>>(p_sc);
    // 10) attn2 = P @ V                  batched 16x [2048,256], K=2048
    sgemm_kernel<false><<<dim3(2, 16, NBATCH), blk>>>(
        p_sc, Ss, (long long)Ss * Ss,
        p_vs, VHD, (long long)Ss * VHD,
        nullptr,
        p_attn2, VHD, (long long)Ss * VHD,
        Ss, VHD, Ss, 1.f);
    // 11) permute to [B*S, H*256]
    permute_kernel<<<(MTOK * 2048) / 256, 256>>>(p_attn2, p_attn);
    // 12) out = attn @ w_o + b           [4096,1024], K=2048
    sgemm_kernel<false><<<dim3(8, 32, 1), blk>>>(
        p_attn, 2048, 0, w_o_w, 1024, 0, w_o_b, out, 1024, 0, MTOK, 1024, 2048, 1.f);
}

// round 7
// speedup vs baseline: 2.4593x; 2.4593x over previous
#include <cuda_runtime.h>
#include <cuda_bf16.h>
#include <math.h>
#include <stdint.h>

// ---------------- problem constants ----------------
#define Bb    2
#define Ss    2048
#define MTOK  4096
#define NBATCH 16

// ---------------- scratch (device globals; no allocation) ----------------
__device__ float g_cq[MTOK * 128];
__device__ float g_q[MTOK * 1024];
__device__ float g_ckvkr[MTOK * 192];
__device__ float g_ckv[MTOK * 128];
__device__ float g_kr[MTOK * 64];
__device__ float g_kv[MTOK * 2560];
__device__ float g_qs[NBATCH * Ss * 128];
__device__ float g_ks[NBATCH * Ss * 128];
__device__ float g_vt[NBATCH * 256 * Ss];                 // V^T per (b,h): [256][2048]
__device__ float g_sc[(long long)NBATCH * Ss * Ss];       // 268 MB
__device__ float g_attn2[NBATCH * Ss * 256];
__device__ float g_attn[MTOK * 2048];
// transposed weights [N][K]
__device__ float g_wt_dq[128 * 1024];
__device__ float g_wt_uq[1024 * 128];
__device__ float g_wt_dkv[192 * 1024];
__device__ float g_wt_ukuv[2560 * 128];
__device__ float g_wt_o[1024 * 2048];

// ================= helpers =================
__device__ __forceinline__ uint32_t smem_u32(const void* p) {
    uint32_t a;
    asm("{ .reg .u64 t; cvta.to.shared.u64 t, %1; cvt.u32.u64 %0, t; }" : "=r"(a) : "l"(p));
    return a;
}

#define LDSM4(r0, r1, r2, r3, addr) \
    asm volatile("ldmatrix.sync.aligned.m8n8.x4.shared.b16 {%0,%1,%2,%3}, [%4];" \
                 : "=r"(r0), "=r"(r1), "=r"(r2), "=r"(r3) : "r"(addr))

#define MMA_BF16(d, a, b) \
    asm volatile("mma.sync.aligned.m16n8k16.row.col.f32.bf16.bf16.f32 " \
                 "{%0,%1,%2,%3}, {%4,%5,%6,%7}, {%8,%9}, {%0,%1,%2,%3};" \
                 : "+f"((d)[0]), "+f"((d)[1]), "+f"((d)[2]), "+f"((d)[3]) \
                 : "r"((a)[0]), "r"((a)[1]), "r"((a)[2]), "r"((a)[3]), \
                   "r"((b)[0]), "r"((b)[1]))

__device__ __forceinline__ void split2(float x, float y, uint32_t& hi, uint32_t& lo) {
    __nv_bfloat16 hx = __float2bfloat16(x), hy = __float2bfloat16(y);
    __nv_bfloat16 lx = __float2bfloat16(x - __bfloat162float(hx));
    __nv_bfloat16 ly = __float2bfloat16(y - __bfloat162float(hy));
    __nv_bfloat162 h = __halves2bfloat162(hx, hy);
    __nv_bfloat162 l = __halves2bfloat162(lx, ly);
    hi = *reinterpret_cast<uint32_t*>(&h);
    lo = *reinterpret_cast<uint32_t*>(&l);
}

// ================= warp-MMA split-bf16 GEMM =================
// C[m,n] = alpha * sum_k A[m,k]*Bt[n,k] + bias[n]; fp32 in/out.
// Block tile 128x128, BK=32, 256 threads (8 warps, 2x4), warp tile 64x32.
// Requirements: M % 128 == 0, K % 32 == 0, N even.
#define SROW 40   // bf16 elems per smem row (32 + 8 pad) = 80 bytes

__global__ void __launch_bounds__(256)
hgemm_kernel(const float* __restrict__ A, int lda, long long sA,
             const float* __restrict__ Bt, int ldb, long long sB,
             const float* __restrict__ bias,
             float* __restrict__ C, int ldc, long long sC,
             int N, int K, float alpha)
{
    __shared__ __align__(16) __nv_bfloat16 sAh[128 * SROW];
    __shared__ __align__(16) __nv_bfloat16 sAl[128 * SROW];
    __shared__ __align__(16) __nv_bfloat16 sBh[128 * SROW];
    __shared__ __align__(16) __nv_bfloat16 sBl[128 * SROW];

    const int tid  = threadIdx.x;
    const int lane = tid & 31;
    const int wid  = tid >> 5;
    const int wm   = wid & 1;        // 0..1 -> m offset 0/64
    const int wn   = wid >> 1;       // 0..3 -> n offset 0/32/64/96

    const int z  = blockIdx.z;
    A  += z * sA;
    Bt += z * sB;
    C  += z * sC;
    const int m0 = blockIdx.y * 128;
    const int n0 = blockIdx.x * 128;

    const uint32_t uAh = smem_u32(sAh), uAl = smem_u32(sAl);
    const uint32_t uBh = smem_u32(sBh), uBl = smem_u32(sBl);

    // loader mapping: thread handles rows {lr, lr+64} x float4 cols {lc4, lc4+1}
    const int lr  = tid >> 2;          // 0..63
    const int lc4 = (tid & 3) * 2;     // 0,2,4,6

    float4 pa[4], pb[4];

    float acc[4][4][4];
#pragma unroll
    for (int i = 0; i < 4; i++)
#pragma unroll
        for (int j = 0; j < 4; j++)
#pragma unroll
            for (int c = 0; c < 4; c++) acc[i][j][c] = 0.f;

    // ---- prefetch first slab ----
#pragma unroll
    for (int u = 0; u < 4; u++) {
        int r  = lr + (u >> 1) * 64;
        int c4 = lc4 + (u & 1);
        pa[u] = *reinterpret_cast<const float4*>(A + (long long)(m0 + r) * lda + c4 * 4);
        int bn = n0 + r;
        pb[u] = (bn < N)
            ? *reinterpret_cast<const float4*>(Bt + (long long)bn * ldb + c4 * 4)
            : make_float4(0.f, 0.f, 0.f, 0.f);
    }

    const int nk = K >> 5;
    for (int s = 0; s < nk; s++) {
        // store current slab to smem (split hi/lo)
#pragma unroll
        for (int u = 0; u < 4; u++) {
            int r = lr + (u >> 1) * 64;
            int c = (lc4 + (u & 1)) * 4;
            uint32_t h0, l0, h1, l1;
            split2(pa[u].x, pa[u].y, h0, l0);
            split2(pa[u].z, pa[u].w, h1, l1);
            *reinterpret_cast<uint32_t*>(&sAh[r * SROW + c])     = h0;
            *reinterpret_cast<uint32_t*>(&sAh[r * SROW + c + 2]) = h1;
            *reinterpret_cast<uint32_t*>(&sAl[r * SROW + c])     = l0;
            *reinterpret_cast<uint32_t*>(&sAl[r * SROW + c + 2]) = l1;
            split2(pb[u].x, pb[u].y, h0, l0);
            split2(pb[u].z, pb[u].w, h1, l1);
            *reinterpret_cast<uint32_t*>(&sBh[r * SROW + c])     = h0;
            *reinterpret_cast<uint32_t*>(&sBh[r * SROW + c + 2]) = h1;
            *reinterpret_cast<uint32_t*>(&sBl[r * SROW + c])     = l0;
            *reinterpret_cast<uint32_t*>(&sBl[r * SROW + c + 2]) = l1;
        }
        __syncthreads();

        // prefetch next slab (overlaps with MMA below)
        if (s + 1 < nk) {
            const int kt = (s + 1) << 5;
#pragma unroll
            for (int u = 0; u < 4; u++) {
                int r  = lr + (u >> 1) * 64;
                int c4 = lc4 + (u & 1);
                pa[u] = *reinterpret_cast<const float4*>(
                    A + (long long)(m0 + r) * lda + kt + c4 * 4);
                int bn = n0 + r;
                pb[u] = (bn < N)
                    ? *reinterpret_cast<const float4*>(
                          Bt + (long long)bn * ldb + kt + c4 * 4)
                    : make_float4(0.f, 0.f, 0.f, 0.f);
            }
        }

        // ---- compute: 2 k16 substeps ----
#pragma unroll
        for (int ks = 0; ks < 2; ks++) {
            // B fragments: 4 n-tiles via two ldmatrix.x4
            uint32_t bh[4][2], bl[4][2];
#pragma unroll
            for (int jp = 0; jp < 2; jp++) {
                int rowb = wn * 32 + jp * 16 + (lane & 7) + ((lane & 16) >> 1);
                int kc   = ks * 16 + (lane & 8);
                uint32_t off = (uint32_t)(rowb * SROW + kc) * 2;
                LDSM4(bh[jp * 2][0], bh[jp * 2][1], bh[jp * 2 + 1][0], bh[jp * 2 + 1][1],
                      uBh + off);
                LDSM4(bl[jp * 2][0], bl[jp * 2][1], bl[jp * 2 + 1][0], bl[jp * 2 + 1][1],
                      uBl + off);
            }
            // A fragments per m-tile, then 3-pass MMA
#pragma unroll
            for (int i = 0; i < 4; i++) {
                int rowa = wm * 64 + i * 16 + (lane & 7) + (lane & 8);
                int kc   = ks * 16 + ((lane & 16) >> 1);
                uint32_t off = (uint32_t)(rowa * SROW + kc) * 2;
                uint32_t ah[4], al[4];
                LDSM4(ah[0], ah[1], ah[2], ah[3], uAh + off);
                LDSM4(al[0], al[1], al[2], al[3], uAl + off);
#pragma unroll
                for (int j = 0; j < 4; j++) {
                    MMA_BF16(acc[i][j], ah, bh[j]);
                    MMA_BF16(acc[i][j], ah, bl[j]);
                    MMA_BF16(acc[i][j], al, bh[j]);
                }
            }
        }
        __syncthreads();
    }

    // ---- epilogue: direct stores (each quad of lanes = one 32B sector) ----
#pragma unroll
    for (int j = 0; j < 4; j++) {
        int col = n0 + wn * 32 + j * 8 + (lane & 3) * 2;
        if (col >= N) continue;
        float b0 = 0.f, b1 = 0.f;
        if (bias) { b0 = bias[col]; b1 = bias[col + 1]; }
#pragma unroll
        for (int i = 0; i < 4; i++) {
            int row = m0 + wm * 64 + i * 16 + (lane >> 2);
            float2 v0 = make_float2(acc[i][j][0] * alpha + b0,
                                    acc[i][j][1] * alpha + b1);
            float2 v1 = make_float2(acc[i][j][2] * alpha + b0,
                                    acc[i][j][3] * alpha + b1);
            *reinterpret_cast<float2*>(C + (long long)row * ldc + col)       = v0;
            *reinterpret_cast<float2*>(C + (long long)(row + 8) * ldc + col) = v1;
        }
    }
}

// ================= transpose kernels =================
__global__ void transpose_kernel(const float* __restrict__ src, int R, int Cc,
                                 float* __restrict__ dst)
{
    __shared__ float t[32][33];
    int r0 = blockIdx.y * 32, c0 = blockIdx.x * 32;
    int tx = threadIdx.x, ty = threadIdx.y;    // 32 x 8
#pragma unroll
    for (int i = 0; i < 32; i += 8)
        if (r0 + ty + i < R && c0 + tx < Cc)
            t[ty + i][tx] = src[(long long)(r0 + ty + i) * Cc + c0 + tx];
    __syncthreads();
#pragma unroll
    for (int i = 0; i < 32; i += 8)
        if (c0 + ty + i < Cc && r0 + tx < R)
            dst[(long long)(c0 + ty + i) * R + r0 + tx] = t[tx][ty + i];
}

// V^T: vt[z][d][s] = kv[(b*2048+s)*2560 + 512 + h*256 + d],  z = b*8+h
__global__ void build_vT_kernel(const float* __restrict__ kv, float* __restrict__ vt)
{
    __shared__ float t[32][33];
    int z = blockIdx.z, b = z >> 3, h = z & 7;
    const float* src = kv + (long long)b * 2048 * 2560 + 512 + h * 256;
    float* dst = vt + (long long)z * 256 * 2048;
    int s0 = blockIdx.x * 32, d0 = blockIdx.y * 32;
    int tx = threadIdx.x, ty = threadIdx.y;
#pragma unroll
    for (int i = 0; i < 32; i += 8)
        t[ty + i][tx] = src[(long long)(s0 + ty + i) * 2560 + d0 + tx];
    __syncthreads();
#pragma unroll
    for (int i = 0; i < 32; i += 8)
        dst[(long long)(d0 + ty + i) * 2048 + s0 + tx] = t[tx][ty + i];
}

// ================= elementwise kernels =================
__global__ void rmsnorm128_kernel(float* __restrict__ buf, const float* __restrict__ w)
{
    int row = blockIdx.x, tid = threadIdx.x;
    float v = buf[row * 128 + tid];
    float ss = v * v;
#pragma unroll
    for (int o = 16; o; o >>= 1) ss += __shfl_xor_sync(0xffffffffu, ss, o);
    __shared__ float red[4];
    if ((tid & 31) == 0) red[tid >> 5] = ss;
    __syncthreads();
    float tot = red[0] + red[1] + red[2] + red[3];
    float rs = rsqrtf(tot * (1.f / 128.f) + 1e-8f);
    buf[row * 128 + tid] = w[tid] * v * rs;
}

__global__ void post_ckvkr_kernel(const float* __restrict__ in,
                                  const float* __restrict__ w,
                                  const int* __restrict__ pos,
                                  float* __restrict__ ckv,
                                  float* __restrict__ kr)
{
    int row = blockIdx.x, tid = threadIdx.x;
    float v = in[row * 192 + tid];
    float ss = v * v;
#pragma unroll
    for (int o = 16; o; o >>= 1) ss += __shfl_xor_sync(0xffffffffu, ss, o);
    __shared__ float red[4];
    if ((tid & 31) == 0) red[tid >> 5] = ss;
    __syncthreads();
    float tot = red[0] + red[1] + red[2] + red[3];
    float rs = rsqrtf(tot * (1.f / 128.f) + 1e-8f);
    ckv[row * 128 + tid] = w[tid] * v * rs;

    if (tid < 32) {
        float xe = in[row * 192 + 128 + 2 * tid];
        float xo = in[row * 192 + 128 + 2 * tid + 1];
        float invf = powf(10000.f, -(float)(2 * tid) / 64.f);
        float ang = (float)pos[row] * invf;
        float s, c;
        sincosf(ang, &s, &c);
        kr[row * 64 + 2 * tid]     = xe * c - xo * s;
        kr[row * 64 + 2 * tid + 1] = xe * s + xo * c;
    }
}

__global__ void build_q_kernel(const float* __restrict__ q,
                               const int* __restrict__ pos,
                               float* __restrict__ qs)
{
    int idx = blockIdx.x * blockDim.x + threadIdx.x;
    int d = idx & 127;
    int t = idx >> 7;
    int qp = t & (Ss - 1);
    int zz = t >> 11;
    int b = zz >> 3, h = zz & 7;
    int row = b * Ss + qp;
    float val;
    if (d < 96) {
        val = q[row * 1024 + h * 96 + d];
    } else {
        int r = d - 96;
        int i = r >> 1;
        float xe = q[row * 1024 + 768 + h * 32 + 2 * i];
        float xo = q[row * 1024 + 768 + h * 32 + 2 * i + 1];
        float invf = powf(10000.f, -(float)(2 * i) / 32.f);
        float ang = (float)pos[row] * invf;
        float s, c;
        sincosf(ang, &s, &c);
        val = (r & 1) ? (xe * s + xo * c) : (xe * c - xo * s);
    }
    qs[idx] = val;
}

__global__ void build_k_kernel(const float* __restrict__ kv,
                               const float* __restrict__ kr,
                               float* __restrict__ ks)
{
    int idx = blockIdx.x * blockDim.x + threadIdx.x;
    int d = idx & 127;
    int t = idx >> 7;
    int qp = t & (Ss - 1);
    int zz = t >> 11;
    int b = zz >> 3, h = zz & 7;
    int row = b * Ss + qp;
    ks[idx] = (d < 64) ? kv[row * 2560 + h * 64 + d] : kr[row * 64 + (d - 64)];
}

__global__ void softmax_kernel(float* __restrict__ sc)
{
    float* p = sc + (long long)blockIdx.x * 2048;
    int tid = threadIdx.x;
    float v[8];
#pragma unroll
    for (int i = 0; i < 8; i++) v[i] = p[tid + 256 * i];
    float m = v[0];
#pragma unroll
    for (int i = 1; i < 8; i++) m = fmaxf(m, v[i]);
#pragma unroll
    for (int o = 16; o; o >>= 1) m = fmaxf(m, __shfl_xor_sync(0xffffffffu, m, o));
    __shared__ float redm[8];
    int lane = tid & 31, w = tid >> 5;
    if (lane == 0) redm[w] = m;
    __syncthreads();
    m = redm[0];
#pragma unroll
    for (int i = 1; i < 8; i++) m = fmaxf(m, redm[i]);
    float sum = 0.f;
#pragma unroll
    for (int i = 0; i < 8; i++) { v[i] = expf(v[i] - m); sum += v[i]; }
#pragma unroll
    for (int o = 16; o; o >>= 1) sum += __shfl_xor_sync(0xffffffffu, sum, o);
    __shared__ float reds[8];
    if (lane == 0) reds[w] = sum;
    __syncthreads();
    sum = 0.f;
#pragma unroll
    for (int i = 0; i < 8; i++) sum += reds[i];
    float inv = 1.f / sum;
#pragma unroll
    for (int i = 0; i < 8; i++) p[tid + 256 * i] = v[i] * inv;
}

__global__ void permute_kernel(const float* __restrict__ a2, float* __restrict__ a)
{
    int idx = blockIdx.x * blockDim.x + threadIdx.x;
    int col = idx & 2047;
    int row = idx >> 11;
    int h = col >> 8;
    int d = col & 255;
    int b = row >> 11;
    int qp = row & (Ss - 1);
    a[idx] = a2[(((b << 3) + h) * Ss + qp) * 256 + d];
}

// ================= launch =================
extern "C" void kernel_launch(void* const* d_in, const int* in_sizes, int n_in,
                              void* d_out, int out_size)
{
    const float* x         = (const float*)d_in[0];
    const int*   pos       = (const int*)  d_in[1];
    const float* w_dq_w    = (const float*)d_in[2];
    const float* w_dq_b    = (const float*)d_in[3];
    const float* q_norm_w  = (const float*)d_in[4];
    const float* w_uq_qr_w = (const float*)d_in[5];
    const float* w_uq_qr_b = (const float*)d_in[6];
    const float* w_dkv_w   = (const float*)d_in[7];
    const float* w_dkv_b   = (const float*)d_in[8];
    const float* kv_norm_w = (const float*)d_in[9];
    const float* w_ukuv_w  = (const float*)d_in[10];
    const float* w_ukuv_b  = (const float*)d_in[11];
    const float* w_o_w     = (const float*)d_in[12];
    const float* w_o_b     = (const float*)d_in[13];
    float* out = (float*)d_out;

    float *p_cq, *p_q, *p_ckvkr, *p_ckv, *p_kr, *p_kv;
    float *p_qs, *p_ks, *p_vt, *p_sc, *p_attn2, *p_attn;
    float *pt_dq, *pt_uq, *pt_dkv, *pt_ukuv, *pt_o;
    cudaGetSymbolAddress((void**)&p_cq,    g_cq);
    cudaGetSymbolAddress((void**)&p_q,     g_q);
    cudaGetSymbolAddress((void**)&p_ckvkr, g_ckvkr);
    cudaGetSymbolAddress((void**)&p_ckv,   g_ckv);
    cudaGetSymbolAddress((void**)&p_kr,    g_kr);
    cudaGetSymbolAddress((void**)&p_kv,    g_kv);
    cudaGetSymbolAddress((void**)&p_qs,    g_qs);
    cudaGetSymbolAddress((void**)&p_ks,    g_ks);
    cudaGetSymbolAddress((void**)&p_vt,    g_vt);
    cudaGetSymbolAddress((void**)&p_sc,    g_sc);
    cudaGetSymbolAddress((void**)&p_attn2, g_attn2);
    cudaGetSymbolAddress((void**)&p_attn,  g_attn);
    cudaGetSymbolAddress((void**)&pt_dq,   g_wt_dq);
    cudaGetSymbolAddress((void**)&pt_uq,   g_wt_uq);
    cudaGetSymbolAddress((void**)&pt_dkv,  g_wt_dkv);
    cudaGetSymbolAddress((void**)&pt_ukuv, g_wt_ukuv);
    cudaGetSymbolAddress((void**)&pt_o,    g_wt_o);

    const float scale = 0.08838834764831845f;   // 1/sqrt(128)
    dim3 tb(32, 8);

    // ---- weight transposes ----
    transpose_kernel<<<dim3(128 / 32, 1024 / 32), tb>>>(w_dq_w,    1024, 128,  pt_dq);
    transpose_kernel<<<dim3(1024 / 32, 128 / 32), tb>>>(w_uq_qr_w, 128, 1024,  pt_uq);
    transpose_kernel<<<dim3(192 / 32, 1024 / 32), tb>>>(w_dkv_w,   1024, 192,  pt_dkv);
    transpose_kernel<<<dim3(2560 / 32, 128 / 32), tb>>>(w_ukuv_w,  128, 2560,  pt_ukuv);
    transpose_kernel<<<dim3(1024 / 32, 2048 / 32), tb>>>(w_o_w,    2048, 1024, pt_o);

    // 1) cq = x @ w_dq + b               [4096,128] K=1024
    hgemm_kernel<<<dim3(1, 32, 1), 256>>>(
        x, 1024, 0, pt_dq, 1024, 0, w_dq_b, p_cq, 128, 0, 128, 1024, 1.f);
    // 2) rmsnorm
    rmsnorm128_kernel<<<MTOK, 128>>>(p_cq, q_norm_w);
    // 3) q = cq @ w_uq + b               [4096,1024] K=128
    hgemm_kernel<<<dim3(8, 32, 1), 256>>>(
        p_cq, 128, 0, pt_uq, 128, 0, w_uq_qr_b, p_q, 1024, 0, 1024, 128, 1.f);
    // 4) ckv_kr = x @ w_dkv + b          [4096,192] K=1024
    hgemm_kernel<<<dim3(2, 32, 1), 256>>>(
        x, 1024, 0, pt_dkv, 1024, 0, w_dkv_b, p_ckvkr, 192, 0, 192, 1024, 1.f);
    // 5) rmsnorm(ckv) + rope(k_rope)
    post_ckvkr_kernel<<<MTOK, 128>>>(p_ckvkr, kv_norm_w, pos, p_ckv, p_kr);
    // 6) kv = ckv @ w_ukuv + b           [4096,2560] K=128
    hgemm_kernel<<<dim3(20, 32, 1), 256>>>(
        p_ckv, 128, 0, pt_ukuv, 128, 0, w_ukuv_b, p_kv, 2560, 0, 2560, 128, 1.f);
    // 7) build q/k states and V^T
    build_q_kernel<<<(NBATCH * Ss * 128) / 256, 256>>>(p_q, pos, p_qs);
    build_k_kernel<<<(NBATCH * Ss * 128) / 256, 256>>>(p_kv, p_kr, p_ks);
    build_vT_kernel<<<dim3(2048 / 32, 256 / 32, NBATCH), tb>>>(p_kv, p_vt);
    // 8) scores = scale * Q @ K^T        16x [2048,2048] K=128
    hgemm_kernel<<<dim3(16, 16, NBATCH), 256>>>(
        p_qs, 128, (long long)Ss * 128,
        p_ks, 128, (long long)Ss * 128,
        nullptr,
        p_sc, Ss, (long long)Ss * Ss,
        Ss, 128, scale);
    // 9) softmax rows
    softmax_kernel<<<NBATCH * Ss, 256>>>(p_sc);
    // 10) attn2 = P @ V                  16x [2048,256] K=2048
    hgemm_kernel<<<dim3(2, 16, NBATCH), 256>>>(
        p_sc, Ss, (long long)Ss * Ss,
        p_vt, Ss, (long long)256 * Ss,
        nullptr,
        p_attn2, 256, (long long)Ss * 256,
        256, Ss, 1.f);
    // 11) permute to [B*S, H*256]
    permute_kernel<<<(MTOK * 2048) / 256, 256>>>(p_attn2, p_attn);
    // 12) out = attn @ w_o + b           [4096,1024] K=2048
    hgemm_kernel<<<dim3(8, 32, 1), 256>>>(
        p_attn, 2048, 0, pt_o, 2048, 0, w_o_b, out, 1024, 0, 1024, 2048, 1.f);
}